// round 9
// baseline (speedup 1.0000x reference)
#include <cuda_runtime.h>
#include <math.h>

#define BATCH  2
#define NTOK   962
#define DIM    384
#define NH     6
#define DH     64
#define NLAYER 12
#define ROWS   (BATCH*NTOK)          // 1924
#define QKVD   (3*DIM)               // 1152
#define HIDD   (4*DIM)               // 1536
#define FEAT_SIZE (ROWS*DIM)         // 738816
#define ATTN_SIZE (BATCH*NH*NTOK*NTOK)

typedef unsigned long long u64;
typedef long long ll;

// ---------------- scratch (static device globals; no allocation) -------------
__device__ float g_x  [ROWS*DIM];
__device__ float g_ln [ROWS*DIM];
__device__ float g_qkv[ROWS*QKVD];
__device__ float g_attn[ATTN_SIZE];     // 44.4 MB scores/probs
__device__ float g_ctx[ROWS*DIM];
__device__ float g_hid[ROWS*HIDD];

// ---------------- packed f32x2 helpers (FFMA2 path, exact fp32) --------------
__device__ __forceinline__ u64 pack_dup(float x) {
    u64 r; asm("mov.b64 %0, {%1, %1};" : "=l"(r) : "f"(x)); return r;
}
__device__ __forceinline__ u64 ffma2(u64 a, u64 b, u64 c) {
    u64 d; asm("fma.rn.f32x2 %0, %1, %2, %3;" : "=l"(d) : "l"(a), "l"(b), "l"(c));
    return d;
}
__device__ __forceinline__ float2 unpack2(u64 a) {
    float2 f; asm("mov.b64 {%0, %1}, %2;" : "=f"(f.x), "=f"(f.y) : "l"(a));
    return f;
}

// ---------------- tiled SGEMM, 128xBN tile, 8x(BN/16) microtile, f32x2 -------
// C[M,N] = act( alpha * A[M,K] @ B(K,N) + bias ) + res
//   TRANSB=false: B row-major [K,N];  TRANSB=true: B row-major [N,K] (A@B^T)
//   A4: vectorized A loads (requires K%16==0 and 16B-aligned A rows)
// Batched over blockIdx.z (z = zb*Hn + zh) with independent strides.
#define TBK 16
#define TBM 128

template<int BN, bool TRANSB, bool A4, bool DOGELU>
__global__ __launch_bounds__(256, 2) void gemm_k(
    const float* __restrict__ A, const float* __restrict__ B,
    const float* __restrict__ bias, const float* __restrict__ res,
    float* __restrict__ C,
    int M, int N, int K, int lda, int ldb, int ldc, int Hn,
    ll sAb, ll sAh, ll sBb, ll sBh, ll sCb, ll sCh, float alpha)
{
    constexpr int TN = BN / 16;      // 8 (BN=128) or 4 (BN=64)
    __shared__ __align__(16) float As[TBK][TBM + 4];
    __shared__ __align__(16) float Bs[TBK][BN + 4];

    const int zb = blockIdx.z / Hn;
    const int zh = blockIdx.z % Hn;
    A += zb * sAb + zh * sAh;
    B += zb * sBb + zh * sBh;
    C += zb * sCb + zh * sCh;

    const int t  = threadIdx.x;
    const int tx = t & 15;
    const int ty = t >> 4;
    const int row0 = blockIdx.y * TBM;
    const int col0 = blockIdx.x * BN;

    u64 acc[4][TN];
    #pragma unroll
    for (int i = 0; i < 4; i++)
        #pragma unroll
        for (int j = 0; j < TN; j++) acc[i][j] = 0ull;

    for (int k0 = 0; k0 < K; k0 += TBK) {
        // ---- A tile: 128x16
        if (A4) {
            #pragma unroll
            for (int i = 0; i < 2; i++) {
                int id = t + i * 256;            // 0..511 float4 slots
                int m = id >> 2;
                int k = (id & 3) * 4;
                int gm = row0 + m;
                float4 v = make_float4(0.f, 0.f, 0.f, 0.f);
                if (gm < M) v = *(const float4*)&A[(ll)gm * lda + k0 + k];
                As[k + 0][m] = v.x; As[k + 1][m] = v.y;
                As[k + 2][m] = v.z; As[k + 3][m] = v.w;
            }
        } else {
            #pragma unroll
            for (int i = 0; i < 8; i++) {
                int id = t + i * 256;            // 0..2047
                int m = id >> 4, k = id & 15;
                int gm = row0 + m, gk = k0 + k;
                As[k][m] = (gm < M && gk < K) ? A[(ll)gm * lda + gk] : 0.f;
            }
        }
        // ---- B tile: 16xBN
        if (TRANSB) {
            #pragma unroll
            for (int i = 0; i < (BN * 4) / 256; i++) {
                int id = t + i * 256;            // BN*4 float4 slots
                int n = id >> 2;
                int k = (id & 3) * 4;
                int gn = col0 + n;
                float4 v = make_float4(0.f, 0.f, 0.f, 0.f);
                if (gn < N) v = *(const float4*)&B[(ll)gn * ldb + k0 + k];
                Bs[k + 0][n] = v.x; Bs[k + 1][n] = v.y;
                Bs[k + 2][n] = v.z; Bs[k + 3][n] = v.w;
            }
        } else {
            constexpr int NB4 = (TBK * BN / 4) / 256;   // 2 or 1
            #pragma unroll
            for (int i = 0; i < NB4; i++) {
                int id = t + i * 256;
                int k = id / (BN / 4);
                int n = (id % (BN / 4)) * 4;
                int gk = k0 + k, gn = col0 + n;
                float4 v = make_float4(0.f, 0.f, 0.f, 0.f);
                if (gk < K && gn < N) v = *(const float4*)&B[(ll)gk * ldb + gn];
                *(float4*)&Bs[k][n] = v;
            }
        }
        __syncthreads();

        #pragma unroll
        for (int kk = 0; kk < TBK; kk++) {
            // A pairs along M: LDS.64 yields packed (lo,hi) f32x2 directly
            const double* arow = (const double*)&As[kk][ty * 8];
            u64 ap0 = __double_as_longlong(arow[0]);
            u64 ap1 = __double_as_longlong(arow[1]);
            u64 ap2 = __double_as_longlong(arow[2]);
            u64 ap3 = __double_as_longlong(arow[3]);
            float bs[TN];
            *(float4*)&bs[0] = *(const float4*)&Bs[kk][tx * TN];
            if (TN == 8) *(float4*)&bs[4] = *(const float4*)&Bs[kk][tx * TN + 4];
            #pragma unroll
            for (int j = 0; j < TN; j++) {
                u64 bd = pack_dup(bs[j]);
                acc[0][j] = ffma2(ap0, bd, acc[0][j]);
                acc[1][j] = ffma2(ap1, bd, acc[1][j]);
                acc[2][j] = ffma2(ap2, bd, acc[2][j]);
                acc[3][j] = ffma2(ap3, bd, acc[3][j]);
            }
        }
        __syncthreads();
    }

    // ---- epilogue
    #pragma unroll
    for (int mp = 0; mp < 4; mp++) {
        int gm0 = row0 + ty * 8 + 2 * mp;
        int gm1 = gm0 + 1;
        #pragma unroll
        for (int j = 0; j < TN; j++) {
            int gn = col0 + tx * TN + j;
            if (gn >= N) continue;
            float2 p = unpack2(acc[mp][j]);
            float bb = bias ? bias[gn] : 0.f;
            if (gm0 < M) {
                float v = p.x * alpha + bb;
                if (DOGELU) v = 0.5f * v * (1.f + erff(v * 0.70710678118654752440f));
                if (res) v += res[(ll)gm0 * ldc + gn];
                C[(ll)gm0 * ldc + gn] = v;
            }
            if (gm1 < M) {
                float v = p.y * alpha + bb;
                if (DOGELU) v = 0.5f * v * (1.f + erff(v * 0.70710678118654752440f));
                if (res) v += res[(ll)gm1 * ldc + gn];
                C[(ll)gm1 * ldc + gn] = v;
            }
        }
    }
}

// ---------------- layernorm: one block per row, D=384 ------------------------
__global__ __launch_bounds__(128) void ln_k(
    const float* __restrict__ x, const float* __restrict__ g,
    const float* __restrict__ b, float* __restrict__ o)
{
    __shared__ float sh[4];
    ll row = blockIdx.x;
    const float* xr = x + row * DIM;
    float* orow = o + row * DIM;
    int t = threadIdx.x;

    float v0 = xr[t], v1 = xr[t + 128], v2 = xr[t + 256];
    float s = v0 + v1 + v2;
    #pragma unroll
    for (int ofs = 16; ofs; ofs >>= 1) s += __shfl_xor_sync(0xffffffffu, s, ofs);
    if ((t & 31) == 0) sh[t >> 5] = s;
    __syncthreads();
    float mean = (sh[0] + sh[1] + sh[2] + sh[3]) * (1.f / DIM);
    __syncthreads();

    float d0 = v0 - mean, d1 = v1 - mean, d2 = v2 - mean;
    float q = d0*d0 + d1*d1 + d2*d2;
    #pragma unroll
    for (int ofs = 16; ofs; ofs >>= 1) q += __shfl_xor_sync(0xffffffffu, q, ofs);
    if ((t & 31) == 0) sh[t >> 5] = q;
    __syncthreads();
    float var = (sh[0] + sh[1] + sh[2] + sh[3]) * (1.f / DIM);
    float r = rsqrtf(var + 1e-6f);

    orow[t]       = d0 * r * g[t]       + b[t];
    orow[t + 128] = d1 * r * g[t + 128] + b[t + 128];
    orow[t + 256] = d2 * r * g[t + 256] + b[t + 256];
}

// ---------------- softmax + threshold mask + renormalize (one block/row) -----
// Reference: p = softmax(s); keep p >= 0.1*max(p); p /= sum(kept).
// max(p) = exp(0)/sum = 1/sum exactly (exp(0)==1.0f), so thresh = 0.1f*(1/sum).
__global__ __launch_bounds__(256) void softmax_k(
    const float* __restrict__ S, float* __restrict__ P)
{
    __shared__ float sh[8];
    ll row = blockIdx.x;
    const float* sr = S + row * NTOK;
    float* pr = P + row * NTOK;
    int t = threadIdx.x;

    float v[4];
    float mx = -3.4e38f;
    #pragma unroll
    for (int i = 0; i < 4; i++) {
        int j = t + i * 256;
        v[i] = (j < NTOK) ? sr[j] : -3.4e38f;
        mx = fmaxf(mx, v[i]);
    }
    #pragma unroll
    for (int ofs = 16; ofs; ofs >>= 1) mx = fmaxf(mx, __shfl_xor_sync(0xffffffffu, mx, ofs));
    if ((t & 31) == 0) sh[t >> 5] = mx;
    __syncthreads();
    float smax = sh[0];
    #pragma unroll
    for (int i = 1; i < 8; i++) smax = fmaxf(smax, sh[i]);
    __syncthreads();

    float sum = 0.f;
    #pragma unroll
    for (int i = 0; i < 4; i++) {
        float e = expf(v[i] - smax);   // OOB lanes: exp(-huge)=0
        v[i] = e;
        sum += e;
    }
    #pragma unroll
    for (int ofs = 16; ofs; ofs >>= 1) sum += __shfl_xor_sync(0xffffffffu, sum, ofs);
    if ((t & 31) == 0) sh[t >> 5] = sum;
    __syncthreads();
    float S1 = sh[0] + sh[1] + sh[2] + sh[3] + sh[4] + sh[5] + sh[6] + sh[7];
    __syncthreads();

    float thresh = 0.1f * (1.0f / S1);
    float sum2 = 0.f;
    #pragma unroll
    for (int i = 0; i < 4; i++) {
        float p = v[i] / S1;
        v[i] = (p >= thresh) ? p : 0.f;
        sum2 += v[i];
    }
    #pragma unroll
    for (int ofs = 16; ofs; ofs >>= 1) sum2 += __shfl_xor_sync(0xffffffffu, sum2, ofs);
    if ((t & 31) == 0) sh[t >> 5] = sum2;
    __syncthreads();
    float S2 = sh[0] + sh[1] + sh[2] + sh[3] + sh[4] + sh[5] + sh[6] + sh[7];

    #pragma unroll
    for (int i = 0; i < 4; i++) {
        int j = t + i * 256;
        if (j < NTOK) pr[j] = v[i] / S2;
    }
}

__global__ void copy_k(const float* __restrict__ a, float* __restrict__ o, int n)
{
    int i = blockIdx.x * 256 + threadIdx.x;
    if (i < n) o[i] = a[i];
}

// -----------------------------------------------------------------------------
extern "C" void kernel_launch(void* const* d_in, const int* in_sizes, int n_in,
                              void* d_out, int out_size)
{
    const float* x_in   = (const float*)d_in[0];
    const float* w_qkv  = (const float*)d_in[1];
    const float* b_qkv  = (const float*)d_in[2];
    const float* w_proj = (const float*)d_in[3];
    const float* b_proj = (const float*)d_in[4];
    const float* ln1g   = (const float*)d_in[5];
    const float* ln1b   = (const float*)d_in[6];
    const float* ln2g   = (const float*)d_in[7];
    const float* ln2b   = (const float*)d_in[8];
    const float* w_fc1  = (const float*)d_in[9];
    const float* b_fc1  = (const float*)d_in[10];
    const float* w_fc2  = (const float*)d_in[11];
    const float* b_fc2  = (const float*)d_in[12];
    const float* lnfg   = (const float*)d_in[13];
    const float* lnfb   = (const float*)d_in[14];

    float* out_feat = (float*)d_out;
    float* out_attn = out_feat + FEAT_SIZE;

    float *x_, *ln_, *qkv_, *attn_, *ctx_, *hid_;
    cudaGetSymbolAddress((void**)&x_,   g_x);
    cudaGetSymbolAddress((void**)&ln_,  g_ln);
    cudaGetSymbolAddress((void**)&qkv_, g_qkv);
    cudaGetSymbolAddress((void**)&attn_, g_attn);
    cudaGetSymbolAddress((void**)&ctx_, g_ctx);
    cudaGetSymbolAddress((void**)&hid_, g_hid);

    copy_k<<<(FEAT_SIZE + 255) / 256, 256>>>(x_in, x_, FEAT_SIZE);

    const int mBlk = (ROWS + TBM - 1) / TBM;          // 16
    const int sBlk = (NTOK + TBM - 1) / TBM;          // 8

    for (int l = 0; l < NLAYER; l++) {
        // LN1
        ln_k<<<ROWS, 128>>>(x_, ln1g + l * DIM, ln1b + l * DIM, ln_);

        // QKV = ln1 @ w_qkv[l] + b_qkv[l]    [1924 x 1152], K=384
        gemm_k<128, false, true, false><<<dim3(QKVD / 128, mBlk, 1), 256>>>(
            ln_, w_qkv + (ll)l * DIM * QKVD, b_qkv + l * QKVD, nullptr, qkv_,
            ROWS, QKVD, DIM, DIM, QKVD, QKVD, 1, 0, 0, 0, 0, 0, 0, 1.f);

        // scores[b,h] = Q @ K^T * dh^-0.5   (12 batches of 962x962x64)
        gemm_k<128, true, true, false><<<dim3(sBlk, sBlk, BATCH * NH), 256>>>(
            qkv_ /*Q*/, qkv_ + DIM /*K*/, nullptr, nullptr, attn_,
            NTOK, NTOK, DH, QKVD, QKVD, NTOK, NH,
            (ll)NTOK * QKVD, DH,
            (ll)NTOK * QKVD, DH,
            (ll)NH * NTOK * NTOK, (ll)NTOK * NTOK, 0.125f);

        // softmax + mask + renorm (last layer writes straight into d_out attn region)
        float* pdst = (l == NLAYER - 1) ? out_attn : attn_;
        softmax_k<<<BATCH * NH * NTOK, 256>>>(attn_, pdst);

        // ctx[b,n,h*64+d] = P @ V   (A = probs, lda=962: scalar A path, K=962)
        gemm_k<64, false, false, false><<<dim3(1, sBlk, BATCH * NH), 256>>>(
            pdst, qkv_ + 2 * DIM /*V*/, nullptr, nullptr, ctx_,
            NTOK, DH, NTOK, NTOK, QKVD, DIM, NH,
            (ll)NH * NTOK * NTOK, (ll)NTOK * NTOK,
            (ll)NTOK * QKVD, DH,
            (ll)NTOK * DIM, DH, 1.f);

        // x += ctx @ w_proj[l] + b_proj[l]   [1924 x 384], K=384
        gemm_k<128, false, true, false><<<dim3(DIM / 128, mBlk, 1), 256>>>(
            ctx_, w_proj + (ll)l * DIM * DIM, b_proj + l * DIM, x_, x_,
            ROWS, DIM, DIM, DIM, DIM, DIM, 1, 0, 0, 0, 0, 0, 0, 1.f);

        // LN2
        ln_k<<<ROWS, 128>>>(x_, ln2g + l * DIM, ln2b + l * DIM, ln_);

        // hid = gelu(ln2 @ w_fc1[l] + b_fc1[l])   [1924 x 1536], K=384
        gemm_k<128, false, true, true><<<dim3(HIDD / 128, mBlk, 1), 256>>>(
            ln_, w_fc1 + (ll)l * DIM * HIDD, b_fc1 + l * HIDD, nullptr, hid_,
            ROWS, HIDD, DIM, DIM, HIDD, HIDD, 1, 0, 0, 0, 0, 0, 0, 1.f);

        // x += hid @ w_fc2[l] + b_fc2[l]   [1924 x 384], K=1536
        gemm_k<128, false, true, false><<<dim3(DIM / 128, mBlk, 1), 256>>>(
            hid_, w_fc2 + (ll)l * HIDD * DIM, b_fc2 + l * DIM, x_, x_,
            ROWS, DIM, HIDD, HIDD, DIM, DIM, 1, 0, 0, 0, 0, 0, 0, 1.f);
    }

    // final LN -> feats
    ln_k<<<ROWS, 128>>>(x_, lnfg, lnfb, out_feat);
}

// round 10
// speedup vs baseline: 1.3118x; 1.3118x over previous
#include <cuda_runtime.h>
#include <math.h>

#define BATCH  2
#define NTOK   962
#define DIM    384
#define NH     6
#define DH     64
#define NLAYER 12
#define ROWS   (BATCH*NTOK)          // 1924
#define QKVD   (3*DIM)               // 1152
#define HIDD   (4*DIM)               // 1536
#define FEAT_SIZE (ROWS*DIM)         // 738816
#define ATTN_SIZE (BATCH*NH*NTOK*NTOK)

typedef unsigned long long u64;
typedef long long ll;

// ---------------- scratch (static device globals; no allocation) -------------
__device__ float g_x  [ROWS*DIM];
__device__ float g_ln [ROWS*DIM];
__device__ float g_qkv[ROWS*QKVD];
__device__ float g_attn[ATTN_SIZE];     // 44.4 MB scores/probs
__device__ float g_ctx[ROWS*DIM];
__device__ float g_hid[ROWS*HIDD];

// ---------------- packed f32x2 helpers (FFMA2 path, exact fp32) --------------
__device__ __forceinline__ u64 pack_dup(float x) {
    u64 r; asm("mov.b64 %0, {%1, %1};" : "=l"(r) : "f"(x)); return r;
}
__device__ __forceinline__ u64 ffma2(u64 a, u64 b, u64 c) {
    u64 d; asm("fma.rn.f32x2 %0, %1, %2, %3;" : "=l"(d) : "l"(a), "l"(b), "l"(c));
    return d;
}
__device__ __forceinline__ float2 unpack2(u64 a) {
    float2 f; asm("mov.b64 {%0, %1}, %2;" : "=f"(f.x), "=f"(f.y) : "l"(a));
    return f;
}

// ---------------- double-buffered SGEMM, 128x64 tile, 8x4 microtile, f32x2 ---
// C[M,N] = act( alpha * A[M,K] @ B(K,N) + bias ) + res
//   TRANSB=false: B row-major [K,N];  TRANSB=true: B row-major [N,K] (A@B^T)
//   A4: vectorized A loads (requires K%16==0 and 16B-aligned A rows)
// Batched over blockIdx.z (z = zb*Hn + zh) with independent strides.
#define TBK 16
#define TBM 128
#define TBN 64

template<bool TRANSB, bool A4, bool DOGELU>
__global__ __launch_bounds__(256, 3) void gemm_k(
    const float* __restrict__ A, const float* __restrict__ B,
    const float* __restrict__ bias, const float* __restrict__ res,
    float* __restrict__ C,
    int M, int N, int K, int lda, int ldb, int ldc, int Hn,
    ll sAb, ll sAh, ll sBb, ll sBh, ll sCb, ll sCh, float alpha)
{
    __shared__ __align__(16) float As[2][TBK][TBM + 4];
    __shared__ __align__(16) float Bs[2][TBK][TBN + 4];

    const int zb = blockIdx.z / Hn;
    const int zh = blockIdx.z % Hn;
    A += zb * sAb + zh * sAh;
    B += zb * sBb + zh * sBh;
    C += zb * sCb + zh * sCh;

    const int t  = threadIdx.x;
    const int tx = t & 15;         // 16 thread-cols * 4 N each
    const int ty = t >> 4;         // 16 thread-rows * 8 M each
    const int row0 = blockIdx.y * TBM;
    const int col0 = blockIdx.x * TBN;

    const int nT = (K + TBK - 1) / TBK;

    u64 acc[4][4];
    #pragma unroll
    for (int i = 0; i < 4; i++)
        #pragma unroll
        for (int j = 0; j < 4; j++) acc[i][j] = 0ull;

    // global-load staging registers
    float4 Ar0, Ar1;       // A4 path
    float  Asc[8];         // scalar-A path
    float4 Br;

    // ------- LOAD_GLOBAL(tile) into staging regs -------
    #define LOAD_GLOBAL(TILE)                                                   \
    {                                                                           \
        int k0 = (TILE) * TBK;                                                  \
        if (A4) {                                                               \
            int m = t >> 2, k = (t & 3) * 4;                                    \
            int gm = row0 + m;                                                  \
            Ar0 = (gm < M) ? *(const float4*)&A[(ll)gm * lda + k0 + k]          \
                           : make_float4(0.f,0.f,0.f,0.f);                      \
            gm = row0 + m + 64;                                                 \
            Ar1 = (gm < M) ? *(const float4*)&A[(ll)gm * lda + k0 + k]          \
                           : make_float4(0.f,0.f,0.f,0.f);                      \
        } else {                                                                \
            _Pragma("unroll")                                                   \
            for (int i = 0; i < 8; i++) {                                       \
                int id = t + i * 256;                                           \
                int m = id >> 4, k = id & 15;                                   \
                int gm = row0 + m, gk = k0 + k;                                 \
                Asc[i] = (gm < M && gk < K) ? A[(ll)gm * lda + gk] : 0.f;       \
            }                                                                   \
        }                                                                       \
        if (TRANSB) {                                                           \
            int n = t >> 2, k = (t & 3) * 4;                                    \
            int gn = col0 + n;                                                  \
            Br = (gn < N) ? *(const float4*)&B[(ll)gn * ldb + k0 + k]           \
                          : make_float4(0.f,0.f,0.f,0.f);                       \
        } else {                                                                \
            int k = t >> 4, n = (t & 15) * 4;                                   \
            int gk = k0 + k, gn = col0 + n;                                     \
            Br = (gk < K && gn < N) ? *(const float4*)&B[(ll)gk * ldb + gn]     \
                                    : make_float4(0.f,0.f,0.f,0.f);             \
        }                                                                       \
    }

    // ------- STORE_SMEM(buf) from staging regs -------
    #define STORE_SMEM(BUF)                                                     \
    {                                                                           \
        if (A4) {                                                               \
            int m = t >> 2, k = (t & 3) * 4;                                    \
            As[BUF][k+0][m] = Ar0.x; As[BUF][k+1][m] = Ar0.y;                   \
            As[BUF][k+2][m] = Ar0.z; As[BUF][k+3][m] = Ar0.w;                   \
            As[BUF][k+0][m+64] = Ar1.x; As[BUF][k+1][m+64] = Ar1.y;             \
            As[BUF][k+2][m+64] = Ar1.z; As[BUF][k+3][m+64] = Ar1.w;             \
        } else {                                                                \
            _Pragma("unroll")                                                   \
            for (int i = 0; i < 8; i++) {                                       \
                int id = t + i * 256;                                           \
                As[BUF][id & 15][id >> 4] = Asc[i];                             \
            }                                                                   \
        }                                                                       \
        if (TRANSB) {                                                           \
            int n = t >> 2, k = (t & 3) * 4;                                    \
            Bs[BUF][k+0][n] = Br.x; Bs[BUF][k+1][n] = Br.y;                     \
            Bs[BUF][k+2][n] = Br.z; Bs[BUF][k+3][n] = Br.w;                     \
        } else {                                                                \
            int k = t >> 4, n = (t & 15) * 4;                                   \
            *(float4*)&Bs[BUF][k][n] = Br;                                      \
        }                                                                       \
    }

    // prologue: tile 0
    LOAD_GLOBAL(0);
    STORE_SMEM(0);
    __syncthreads();

    for (int tt = 0; tt < nT; tt++) {
        const int cur = tt & 1;
        const bool more = (tt + 1 < nT);
        if (more) LOAD_GLOBAL(tt + 1);

        #pragma unroll
        for (int kk = 0; kk < TBK; kk++) {
            const double* arow = (const double*)&As[cur][kk][ty * 8];
            u64 ap0 = __double_as_longlong(arow[0]);
            u64 ap1 = __double_as_longlong(arow[1]);
            u64 ap2 = __double_as_longlong(arow[2]);
            u64 ap3 = __double_as_longlong(arow[3]);
            float4 bq = *(const float4*)&Bs[cur][kk][tx * 4];
            u64 b0 = pack_dup(bq.x);
            u64 b1 = pack_dup(bq.y);
            u64 b2 = pack_dup(bq.z);
            u64 b3 = pack_dup(bq.w);
            acc[0][0] = ffma2(ap0, b0, acc[0][0]);
            acc[1][0] = ffma2(ap1, b0, acc[1][0]);
            acc[2][0] = ffma2(ap2, b0, acc[2][0]);
            acc[3][0] = ffma2(ap3, b0, acc[3][0]);
            acc[0][1] = ffma2(ap0, b1, acc[0][1]);
            acc[1][1] = ffma2(ap1, b1, acc[1][1]);
            acc[2][1] = ffma2(ap2, b1, acc[2][1]);
            acc[3][1] = ffma2(ap3, b1, acc[3][1]);
            acc[0][2] = ffma2(ap0, b2, acc[0][2]);
            acc[1][2] = ffma2(ap1, b2, acc[1][2]);
            acc[2][2] = ffma2(ap2, b2, acc[2][2]);
            acc[3][2] = ffma2(ap3, b2, acc[3][2]);
            acc[0][3] = ffma2(ap0, b3, acc[0][3]);
            acc[1][3] = ffma2(ap1, b3, acc[1][3]);
            acc[2][3] = ffma2(ap2, b3, acc[2][3]);
            acc[3][3] = ffma2(ap3, b3, acc[3][3]);
        }

        if (more) {
            STORE_SMEM((tt + 1) & 1);
            __syncthreads();
        }
    }
    #undef LOAD_GLOBAL
    #undef STORE_SMEM

    // ---- epilogue
    #pragma unroll
    for (int mp = 0; mp < 4; mp++) {
        int gm0 = row0 + ty * 8 + 2 * mp;
        int gm1 = gm0 + 1;
        #pragma unroll
        for (int j = 0; j < 4; j++) {
            int gn = col0 + tx * 4 + j;
            if (gn >= N) continue;
            float2 p = unpack2(acc[mp][j]);
            float bb = bias ? bias[gn] : 0.f;
            if (gm0 < M) {
                float v = p.x * alpha + bb;
                if (DOGELU) v = 0.5f * v * (1.f + erff(v * 0.70710678118654752440f));
                if (res) v += res[(ll)gm0 * ldc + gn];
                C[(ll)gm0 * ldc + gn] = v;
            }
            if (gm1 < M) {
                float v = p.y * alpha + bb;
                if (DOGELU) v = 0.5f * v * (1.f + erff(v * 0.70710678118654752440f));
                if (res) v += res[(ll)gm1 * ldc + gn];
                C[(ll)gm1 * ldc + gn] = v;
            }
        }
    }
}

// ---------------- layernorm: one block per row, D=384 ------------------------
__global__ __launch_bounds__(128) void ln_k(
    const float* __restrict__ x, const float* __restrict__ g,
    const float* __restrict__ b, float* __restrict__ o)
{
    __shared__ float sh[4];
    ll row = blockIdx.x;
    const float* xr = x + row * DIM;
    float* orow = o + row * DIM;
    int t = threadIdx.x;

    float v0 = xr[t], v1 = xr[t + 128], v2 = xr[t + 256];
    float s = v0 + v1 + v2;
    #pragma unroll
    for (int ofs = 16; ofs; ofs >>= 1) s += __shfl_xor_sync(0xffffffffu, s, ofs);
    if ((t & 31) == 0) sh[t >> 5] = s;
    __syncthreads();
    float mean = (sh[0] + sh[1] + sh[2] + sh[3]) * (1.f / DIM);
    __syncthreads();

    float d0 = v0 - mean, d1 = v1 - mean, d2 = v2 - mean;
    float q = d0*d0 + d1*d1 + d2*d2;
    #pragma unroll
    for (int ofs = 16; ofs; ofs >>= 1) q += __shfl_xor_sync(0xffffffffu, q, ofs);
    if ((t & 31) == 0) sh[t >> 5] = q;
    __syncthreads();
    float var = (sh[0] + sh[1] + sh[2] + sh[3]) * (1.f / DIM);
    float r = rsqrtf(var + 1e-6f);

    orow[t]       = d0 * r * g[t]       + b[t];
    orow[t + 128] = d1 * r * g[t + 128] + b[t + 128];
    orow[t + 256] = d2 * r * g[t + 256] + b[t + 256];
}

// ---------------- softmax + threshold mask + renormalize (one block/row) -----
// Reference: p = softmax(s); keep p >= 0.1*max(p); p /= sum(kept).
// max(p) = exp(0)/sum = 1/sum exactly (exp(0)==1.0f), so thresh = 0.1f*(1/sum).
__global__ __launch_bounds__(256) void softmax_k(
    const float* __restrict__ S, float* __restrict__ P)
{
    __shared__ float sh[8];
    ll row = blockIdx.x;
    const float* sr = S + row * NTOK;
    float* pr = P + row * NTOK;
    int t = threadIdx.x;

    float v[4];
    float mx = -3.4e38f;
    #pragma unroll
    for (int i = 0; i < 4; i++) {
        int j = t + i * 256;
        v[i] = (j < NTOK) ? sr[j] : -3.4e38f;
        mx = fmaxf(mx, v[i]);
    }
    #pragma unroll
    for (int ofs = 16; ofs; ofs >>= 1) mx = fmaxf(mx, __shfl_xor_sync(0xffffffffu, mx, ofs));
    if ((t & 31) == 0) sh[t >> 5] = mx;
    __syncthreads();
    float smax = sh[0];
    #pragma unroll
    for (int i = 1; i < 8; i++) smax = fmaxf(smax, sh[i]);
    __syncthreads();

    float sum = 0.f;
    #pragma unroll
    for (int i = 0; i < 4; i++) {
        float e = expf(v[i] - smax);   // OOB lanes: exp(-huge)=0
        v[i] = e;
        sum += e;
    }
    #pragma unroll
    for (int ofs = 16; ofs; ofs >>= 1) sum += __shfl_xor_sync(0xffffffffu, sum, ofs);
    if ((t & 31) == 0) sh[t >> 5] = sum;
    __syncthreads();
    float S1 = sh[0] + sh[1] + sh[2] + sh[3] + sh[4] + sh[5] + sh[6] + sh[7];
    __syncthreads();

    float thresh = 0.1f * (1.0f / S1);
    float sum2 = 0.f;
    #pragma unroll
    for (int i = 0; i < 4; i++) {
        float p = v[i] / S1;
        v[i] = (p >= thresh) ? p : 0.f;
        sum2 += v[i];
    }
    #pragma unroll
    for (int ofs = 16; ofs; ofs >>= 1) sum2 += __shfl_xor_sync(0xffffffffu, sum2, ofs);
    if ((t & 31) == 0) sh[t >> 5] = sum2;
    __syncthreads();
    float S2 = sh[0] + sh[1] + sh[2] + sh[3] + sh[4] + sh[5] + sh[6] + sh[7];

    #pragma unroll
    for (int i = 0; i < 4; i++) {
        int j = t + i * 256;
        if (j < NTOK) pr[j] = v[i] / S2;
    }
}

__global__ void copy_k(const float* __restrict__ a, float* __restrict__ o, int n)
{
    int i = blockIdx.x * 256 + threadIdx.x;
    if (i < n) o[i] = a[i];
}

// -----------------------------------------------------------------------------
extern "C" void kernel_launch(void* const* d_in, const int* in_sizes, int n_in,
                              void* d_out, int out_size)
{
    const float* x_in   = (const float*)d_in[0];
    const float* w_qkv  = (const float*)d_in[1];
    const float* b_qkv  = (const float*)d_in[2];
    const float* w_proj = (const float*)d_in[3];
    const float* b_proj = (const float*)d_in[4];
    const float* ln1g   = (const float*)d_in[5];
    const float* ln1b   = (const float*)d_in[6];
    const float* ln2g   = (const float*)d_in[7];
    const float* ln2b   = (const float*)d_in[8];
    const float* w_fc1  = (const float*)d_in[9];
    const float* b_fc1  = (const float*)d_in[10];
    const float* w_fc2  = (const float*)d_in[11];
    const float* b_fc2  = (const float*)d_in[12];
    const float* lnfg   = (const float*)d_in[13];
    const float* lnfb   = (const float*)d_in[14];

    float* out_feat = (float*)d_out;
    float* out_attn = out_feat + FEAT_SIZE;

    float *x_, *ln_, *qkv_, *attn_, *ctx_, *hid_;
    cudaGetSymbolAddress((void**)&x_,   g_x);
    cudaGetSymbolAddress((void**)&ln_,  g_ln);
    cudaGetSymbolAddress((void**)&qkv_, g_qkv);
    cudaGetSymbolAddress((void**)&attn_, g_attn);
    cudaGetSymbolAddress((void**)&ctx_, g_ctx);
    cudaGetSymbolAddress((void**)&hid_, g_hid);

    copy_k<<<(FEAT_SIZE + 255) / 256, 256>>>(x_in, x_, FEAT_SIZE);

    const int mBlk = (ROWS + TBM - 1) / TBM;          // 16
    const int sBlk = (NTOK + TBM - 1) / TBM;          // 8

    for (int l = 0; l < NLAYER; l++) {
        // LN1
        ln_k<<<ROWS, 128>>>(x_, ln1g + l * DIM, ln1b + l * DIM, ln_);

        // QKV = ln1 @ w_qkv[l] + b_qkv[l]    [1924 x 1152], K=384
        gemm_k<false, true, false><<<dim3(QKVD / TBN, mBlk, 1), 256>>>(
            ln_, w_qkv + (ll)l * DIM * QKVD, b_qkv + l * QKVD, nullptr, qkv_,
            ROWS, QKVD, DIM, DIM, QKVD, QKVD, 1, 0, 0, 0, 0, 0, 0, 1.f);

        // scores[b,h] = Q @ K^T * dh^-0.5   (12 batches of 962x962x64)
        gemm_k<true, true, false><<<dim3((NTOK + TBN - 1) / TBN, sBlk, BATCH * NH), 256>>>(
            qkv_ /*Q*/, qkv_ + DIM /*K*/, nullptr, nullptr, attn_,
            NTOK, NTOK, DH, QKVD, QKVD, NTOK, NH,
            (ll)NTOK * QKVD, DH,
            (ll)NTOK * QKVD, DH,
            (ll)NH * NTOK * NTOK, (ll)NTOK * NTOK, 0.125f);

        // softmax + mask + renorm (last layer writes straight into d_out attn region)
        float* pdst = (l == NLAYER - 1) ? out_attn : attn_;
        softmax_k<<<BATCH * NH * NTOK, 256>>>(attn_, pdst);

        // ctx[b,n,h*64+d] = P @ V   (A = probs, lda=962: scalar A path, K=962)
        gemm_k<false, false, false><<<dim3(1, sBlk, BATCH * NH), 256>>>(
            pdst, qkv_ + 2 * DIM /*V*/, nullptr, nullptr, ctx_,
            NTOK, DH, NTOK, NTOK, QKVD, DIM, NH,
            (ll)NH * NTOK * NTOK, (ll)NTOK * NTOK,
            (ll)NTOK * QKVD, DH,
            (ll)NTOK * DIM, DH, 1.f);

        // x += ctx @ w_proj[l] + b_proj[l]   [1924 x 384], K=384
        gemm_k<false, true, false><<<dim3(DIM / TBN, mBlk, 1), 256>>>(
            ctx_, w_proj + (ll)l * DIM * DIM, b_proj + l * DIM, x_, x_,
            ROWS, DIM, DIM, DIM, DIM, DIM, 1, 0, 0, 0, 0, 0, 0, 1.f);

        // LN2
        ln_k<<<ROWS, 128>>>(x_, ln2g + l * DIM, ln2b + l * DIM, ln_);

        // hid = gelu(ln2 @ w_fc1[l] + b_fc1[l])   [1924 x 1536], K=384
        gemm_k<false, true, true><<<dim3(HIDD / TBN, mBlk, 1), 256>>>(
            ln_, w_fc1 + (ll)l * DIM * HIDD, b_fc1 + l * HIDD, nullptr, hid_,
            ROWS, HIDD, DIM, DIM, HIDD, HIDD, 1, 0, 0, 0, 0, 0, 0, 1.f);

        // x += hid @ w_fc2[l] + b_fc2[l]   [1924 x 384], K=1536
        gemm_k<false, true, false><<<dim3(DIM / TBN, mBlk, 1), 256>>>(
            hid_, w_fc2 + (ll)l * HIDD * DIM, b_fc2 + l * DIM, x_, x_,
            ROWS, DIM, HIDD, HIDD, DIM, DIM, 1, 0, 0, 0, 0, 0, 0, 1.f);
    }

    // final LN -> feats
    ln_k<<<ROWS, 128>>>(x_, lnfg, lnfb, out_feat);
}

// round 12
// speedup vs baseline: 1.7329x; 1.3210x over previous
#include <cuda_runtime.h>
#include <cuda_bf16.h>
#include <math.h>

#define BATCH  2
#define NTOK   962
#define DIM    384
#define NH     6
#define DH     64
#define NLAYER 12
#define ROWS   (BATCH*NTOK)          // 1924
#define QKVD   (3*DIM)               // 1152
#define HIDD   (4*DIM)               // 1536
#define FEAT_SIZE (ROWS*DIM)         // 738816
#define ATTN_SIZE (BATCH*NH*NTOK*NTOK)

typedef unsigned long long u64;
typedef unsigned int u32;
typedef long long ll;

// ---------------- scratch (static device globals; no allocation) -------------
__device__ float g_x  [ROWS*DIM];
__device__ float g_ln [ROWS*DIM];
__device__ float g_qkv[ROWS*QKVD];
__device__ float g_attn[ATTN_SIZE];     // 44.4 MB scores/probs
__device__ float g_ctx[ROWS*DIM];
__device__ float g_hid[ROWS*HIDD];

// ---------------- packed f32x2 helpers (FFMA2 path, exact fp32) --------------
__device__ __forceinline__ u64 pack_dup(float x) {
    u64 r; asm("mov.b64 %0, {%1, %1};" : "=l"(r) : "f"(x)); return r;
}
__device__ __forceinline__ u64 ffma2(u64 a, u64 b, u64 c) {
    u64 d; asm("fma.rn.f32x2 %0, %1, %2, %3;" : "=l"(d) : "l"(a), "l"(b), "l"(c));
    return d;
}
__device__ __forceinline__ float2 unpack2(u64 a) {
    float2 f; asm("mov.b64 {%0, %1}, %2;" : "=f"(f.x), "=f"(f.y) : "l"(a));
    return f;
}

// ---------------- bf16 split helpers -----------------------------------------
// split fp32 pair -> (hi bf16x2, lo bf16x2); element0 (x) in low 16 bits.
__device__ __forceinline__ void split2(float x, float y, u32& hi, u32& lo) {
    __nv_bfloat162 h = __floats2bfloat162_rn(x, y);
    float rx = x - __bfloat162float(h.x);
    float ry = y - __bfloat162float(h.y);
    __nv_bfloat162 l = __floats2bfloat162_rn(rx, ry);
    hi = *(u32*)&h; lo = *(u32*)&l;
}

// warp-level bf16 mma (base sm_80+ instruction; no 'a'-features needed)
__device__ __forceinline__ void mma16816(float c[4],
    u32 a0, u32 a1, u32 a2, u32 a3, u32 b0, u32 b1)
{
    asm volatile(
        "mma.sync.aligned.m16n8k16.row.col.f32.bf16.bf16.f32 "
        "{%0,%1,%2,%3}, {%4,%5,%6,%7}, {%8,%9}, {%0,%1,%2,%3};"
        : "+f"(c[0]), "+f"(c[1]), "+f"(c[2]), "+f"(c[3])
        : "r"(a0), "r"(a1), "r"(a2), "r"(a3), "r"(b0), "r"(b1));
}

// ---------------- tensor-core dense GEMM via mma.sync (split-bf16) -----------
// C[M,N] = act(A[M,K] @ B[K,N] + bias) + res.  A row-major lda=K, B row-major
// ldb=N, C row-major ldc=N.  Requires K % 32 == 0, N % 64 == 0.
// CTA: 256 thr = 8 warps (4M x 2N); tile 128(M) x 64(N); K-chunks of 32.
// Split scheme: D += Ah*Bh + Ah*Bl + Al*Bh  (Al*Bl dropped, ~2^-18 rel).
// Smem pair layout: per 8-pair group, column order [0,4,1,5,2,6,3,7] so the
// fragment pairs (t, t+4) are one LDS.64; row stride 24 u32 -> conflict-free.
#define ASTR 24
template<bool DOGELU, bool HASRES>
__global__ __launch_bounds__(256) void mma_gemm(
    const float* __restrict__ A, const float* __restrict__ B,
    const float* __restrict__ bias, const float* __restrict__ res,
    float* __restrict__ C, int M, int N, int K)
{
    __shared__ __align__(16) u32 Ah[128 * ASTR];
    __shared__ __align__(16) u32 Al[128 * ASTR];
    __shared__ __align__(16) u32 Bh[64 * ASTR];
    __shared__ __align__(16) u32 Bl[64 * ASTR];

    const int t = threadIdx.x;
    const int lane = t & 31, wid = t >> 5;
    const int g = lane >> 2, tg = lane & 3;
    const int mw = wid & 3, nw = wid >> 2;
    const int row0 = blockIdx.y * 128;
    const int n0 = blockIdx.x * 64;

    float acc[2][4][4];
    #pragma unroll
    for (int i = 0; i < 2; i++)
        #pragma unroll
        for (int j = 0; j < 4; j++)
            #pragma unroll
            for (int k = 0; k < 4; k++) acc[i][j][k] = 0.f;

    float4 Ar[4];
    float2 Br0[2], Br1[2];

    const int nC = K >> 5;   // chunks of 32

    auto LOADG = [&](int c) {
        int kb = c << 5;
        #pragma unroll
        for (int i = 0; i < 4; i++) {
            int id = t + (i << 8);
            int m = id >> 3, k4 = (id & 7) << 2;
            int gm = row0 + m;
            Ar[i] = (gm < M) ? *(const float4*)&A[(ll)gm * K + kb + k4]
                             : make_float4(0.f, 0.f, 0.f, 0.f);
        }
        #pragma unroll
        for (int i = 0; i < 2; i++) {
            int u = t + (i << 8);
            int kp = u >> 5, n2 = u & 31;
            const float* bp = &B[(ll)(kb + 2 * kp) * N + n0 + 2 * n2];
            Br0[i] = *(const float2*)bp;
            Br1[i] = *(const float2*)(bp + N);
        }
    };
    auto CONVST = [&]() {
        #pragma unroll
        for (int i = 0; i < 4; i++) {
            int id = t + (i << 8);
            int m = id >> 3, k4 = (id & 7) << 2;
            int p0 = k4 >> 1;                 // even pair index (0..14)
            int s = p0 >> 3;
            int pg0 = p0 & 7, pg1 = (p0 + 1) & 7;
            int c0 = s * 8 + ((pg0 & 3) * 2 + (pg0 >> 2));
            int c1 = s * 8 + ((pg1 & 3) * 2 + (pg1 >> 2));
            u32 h0, l0, h1, l1;
            split2(Ar[i].x, Ar[i].y, h0, l0);
            split2(Ar[i].z, Ar[i].w, h1, l1);
            Ah[m * ASTR + c0] = h0; Ah[m * ASTR + c1] = h1;
            Al[m * ASTR + c0] = l0; Al[m * ASTR + c1] = l1;
        }
        #pragma unroll
        for (int i = 0; i < 2; i++) {
            int u = t + (i << 8);
            int kp = u >> 5, n2 = u & 31;
            int s = kp >> 3, pg = kp & 7;
            int cc = s * 8 + ((pg & 3) * 2 + (pg >> 2));
            u32 h0, l0, h1, l1;
            split2(Br0[i].x, Br1[i].x, h0, l0);   // n = 2*n2 (k even -> low)
            split2(Br0[i].y, Br1[i].y, h1, l1);   // n = 2*n2+1
            Bh[(2 * n2) * ASTR + cc] = h0;     Bl[(2 * n2) * ASTR + cc] = l0;
            Bh[(2 * n2 + 1) * ASTR + cc] = h1; Bl[(2 * n2 + 1) * ASTR + cc] = l1;
        }
    };

    LOADG(0); CONVST();
    __syncthreads();

    for (int c = 0; c < nC; c++) {
        const bool more = (c + 1 < nC);
        if (more) LOADG(c + 1);

        #pragma unroll
        for (int s = 0; s < 2; s++) {
            const int co = s * 8 + 2 * tg;
            uint2 AH0[2], AH1[2], AL0[2], AL1[2];
            #pragma unroll
            for (int mt = 0; mt < 2; mt++) {
                int rb = (mw * 32 + mt * 16 + g) * ASTR + co;
                AH0[mt] = *(const uint2*)&Ah[rb];
                AH1[mt] = *(const uint2*)&Ah[rb + 8 * ASTR];
                AL0[mt] = *(const uint2*)&Al[rb];
                AL1[mt] = *(const uint2*)&Al[rb + 8 * ASTR];
            }
            uint2 BHf[4], BLf[4];
            #pragma unroll
            for (int nt = 0; nt < 4; nt++) {
                int rb = (nw * 32 + nt * 8 + g) * ASTR + co;
                BHf[nt] = *(const uint2*)&Bh[rb];
                BLf[nt] = *(const uint2*)&Bl[rb];
            }
            #pragma unroll
            for (int mt = 0; mt < 2; mt++) {
                #pragma unroll
                for (int nt = 0; nt < 4; nt++) {
                    mma16816(acc[mt][nt], AH0[mt].x, AH1[mt].x, AH0[mt].y, AH1[mt].y,
                             BHf[nt].x, BHf[nt].y);
                    mma16816(acc[mt][nt], AH0[mt].x, AH1[mt].x, AH0[mt].y, AH1[mt].y,
                             BLf[nt].x, BLf[nt].y);
                    mma16816(acc[mt][nt], AL0[mt].x, AL1[mt].x, AL0[mt].y, AL1[mt].y,
                             BHf[nt].x, BHf[nt].y);
                }
            }
        }

        __syncthreads();
        if (more) {
            CONVST();
            __syncthreads();
        }
    }

    // ---- epilogue: c0,c1 = row g cols 2t,2t+1; c2,c3 = row g+8
    #pragma unroll
    for (int mt = 0; mt < 2; mt++) {
        #pragma unroll
        for (int half = 0; half < 2; half++) {
            int gm = row0 + mw * 32 + mt * 16 + half * 8 + g;
            if (gm >= M) continue;
            float* crow = &C[(ll)gm * N];
            const float* rrow = HASRES ? &res[(ll)gm * N] : nullptr;
            #pragma unroll
            for (int nt = 0; nt < 4; nt++) {
                int gn = n0 + nw * 32 + nt * 8 + 2 * tg;
                float v0 = acc[mt][nt][half * 2 + 0] + bias[gn];
                float v1 = acc[mt][nt][half * 2 + 1] + bias[gn + 1];
                if (DOGELU) {
                    v0 = 0.5f * v0 * (1.f + erff(v0 * 0.70710678118654752440f));
                    v1 = 0.5f * v1 * (1.f + erff(v1 * 0.70710678118654752440f));
                }
                if (HASRES) { v0 += rrow[gn]; v1 += rrow[gn + 1]; }
                *(float2*)&crow[gn] = make_float2(v0, v1);
            }
        }
    }
}

// ---------------- double-buffered SGEMM (FFMA2) for attention GEMMs ---------
#define TBK 16
#define TBM 128
#define TBN 64

template<bool TRANSB, bool A4, bool DOGELU>
__global__ __launch_bounds__(256, 3) void gemm_k(
    const float* __restrict__ A, const float* __restrict__ B,
    const float* __restrict__ bias, const float* __restrict__ res,
    float* __restrict__ C,
    int M, int N, int K, int lda, int ldb, int ldc, int Hn,
    ll sAb, ll sAh, ll sBb, ll sBh, ll sCb, ll sCh, float alpha)
{
    __shared__ __align__(16) float As[2][TBK][TBM + 4];
    __shared__ __align__(16) float Bs[2][TBK][TBN + 4];

    const int zb = blockIdx.z / Hn;
    const int zh = blockIdx.z % Hn;
    A += zb * sAb + zh * sAh;
    B += zb * sBb + zh * sBh;
    C += zb * sCb + zh * sCh;

    const int t  = threadIdx.x;
    const int tx = t & 15;
    const int ty = t >> 4;
    const int row0 = blockIdx.y * TBM;
    const int col0 = blockIdx.x * TBN;

    const int nT = (K + TBK - 1) / TBK;

    u64 acc[4][4];
    #pragma unroll
    for (int i = 0; i < 4; i++)
        #pragma unroll
        for (int j = 0; j < 4; j++) acc[i][j] = 0ull;

    float4 Ar0, Ar1;
    float  Asc[8];
    float4 Br;

    #define LOAD_GLOBAL(TILE)                                                   \
    {                                                                           \
        int k0 = (TILE) * TBK;                                                  \
        if (A4) {                                                               \
            int m = t >> 2, k = (t & 3) * 4;                                    \
            int gm = row0 + m;                                                  \
            Ar0 = (gm < M) ? *(const float4*)&A[(ll)gm * lda + k0 + k]          \
                           : make_float4(0.f,0.f,0.f,0.f);                      \
            gm = row0 + m + 64;                                                 \
            Ar1 = (gm < M) ? *(const float4*)&A[(ll)gm * lda + k0 + k]          \
                           : make_float4(0.f,0.f,0.f,0.f);                      \
        } else {                                                                \
            _Pragma("unroll")                                                   \
            for (int i = 0; i < 8; i++) {                                       \
                int id = t + i * 256;                                           \
                int m = id >> 4, k = id & 15;                                   \
                int gm = row0 + m, gk = k0 + k;                                 \
                Asc[i] = (gm < M && gk < K) ? A[(ll)gm * lda + gk] : 0.f;       \
            }                                                                   \
        }                                                                       \
        if (TRANSB) {                                                           \
            int n = t >> 2, k = (t & 3) * 4;                                    \
            int gn = col0 + n;                                                  \
            Br = (gn < N) ? *(const float4*)&B[(ll)gn * ldb + k0 + k]           \
                          : make_float4(0.f,0.f,0.f,0.f);                       \
        } else {                                                                \
            int k = t >> 4, n = (t & 15) * 4;                                   \
            int gk = k0 + k, gn = col0 + n;                                     \
            Br = (gk < K && gn < N) ? *(const float4*)&B[(ll)gk * ldb + gn]     \
                                    : make_float4(0.f,0.f,0.f,0.f);             \
        }                                                                       \
    }

    #define STORE_SMEM(BUF)                                                     \
    {                                                                           \
        if (A4) {                                                               \
            int m = t >> 2, k = (t & 3) * 4;                                    \
            As[BUF][k+0][m] = Ar0.x; As[BUF][k+1][m] = Ar0.y;                   \
            As[BUF][k+2][m] = Ar0.z; As[BUF][k+3][m] = Ar0.w;                   \
            As[BUF][k+0][m+64] = Ar1.x; As[BUF][k+1][m+64] = Ar1.y;             \
            As[BUF][k+2][m+64] = Ar1.z; As[BUF][k+3][m+64] = Ar1.w;             \
        } else {                                                                \
            _Pragma("unroll")                                                   \
            for (int i = 0; i < 8; i++) {                                       \
                int id = t + i * 256;                                           \
                As[BUF][id & 15][id >> 4] = Asc[i];                             \
            }                                                                   \
        }                                                                       \
        if (TRANSB) {                                                           \
            int n = t >> 2, k = (t & 3) * 4;                                    \
            Bs[BUF][k+0][n] = Br.x; Bs[BUF][k+1][n] = Br.y;                     \
            Bs[BUF][k+2][n] = Br.z; Bs[BUF][k+3][n] = Br.w;                     \
        } else {                                                                \
            int k = t >> 4, n = (t & 15) * 4;                                   \
            *(float4*)&Bs[BUF][k][n] = Br;                                      \
        }                                                                       \
    }

    LOAD_GLOBAL(0);
    STORE_SMEM(0);
    __syncthreads();

    for (int tt = 0; tt < nT; tt++) {
        const int cur = tt & 1;
        const bool more = (tt + 1 < nT);
        if (more) LOAD_GLOBAL(tt + 1);

        #pragma unroll
        for (int kk = 0; kk < TBK; kk++) {
            const double* arow = (const double*)&As[cur][kk][ty * 8];
            u64 ap0 = __double_as_longlong(arow[0]);
            u64 ap1 = __double_as_longlong(arow[1]);
            u64 ap2 = __double_as_longlong(arow[2]);
            u64 ap3 = __double_as_longlong(arow[3]);
            float4 bq = *(const float4*)&Bs[cur][kk][tx * 4];
            u64 b0 = pack_dup(bq.x);
            u64 b1 = pack_dup(bq.y);
            u64 b2 = pack_dup(bq.z);
            u64 b3 = pack_dup(bq.w);
            acc[0][0] = ffma2(ap0, b0, acc[0][0]);
            acc[1][0] = ffma2(ap1, b0, acc[1][0]);
            acc[2][0] = ffma2(ap2, b0, acc[2][0]);
            acc[3][0] = ffma2(ap3, b0, acc[3][0]);
            acc[0][1] = ffma2(ap0, b1, acc[0][1]);
            acc[1][1] = ffma2(ap1, b1, acc[1][1]);
            acc[2][1] = ffma2(ap2, b1, acc[2][1]);
            acc[3][1] = ffma2(ap3, b1, acc[3][1]);
            acc[0][2] = ffma2(ap0, b2, acc[0][2]);
            acc[1][2] = ffma2(ap1, b2, acc[1][2]);
            acc[2][2] = ffma2(ap2, b2, acc[2][2]);
            acc[3][2] = ffma2(ap3, b2, acc[3][2]);
            acc[0][3] = ffma2(ap0, b3, acc[0][3]);
            acc[1][3] = ffma2(ap1, b3, acc[1][3]);
            acc[2][3] = ffma2(ap2, b3, acc[2][3]);
            acc[3][3] = ffma2(ap3, b3, acc[3][3]);
        }

        if (more) {
            STORE_SMEM((tt + 1) & 1);
            __syncthreads();
        }
    }
    #undef LOAD_GLOBAL
    #undef STORE_SMEM

    #pragma unroll
    for (int mp = 0; mp < 4; mp++) {
        int gm0 = row0 + ty * 8 + 2 * mp;
        int gm1 = gm0 + 1;
        #pragma unroll
        for (int j = 0; j < 4; j++) {
            int gn = col0 + tx * 4 + j;
            if (gn >= N) continue;
            float2 p = unpack2(acc[mp][j]);
            float bb = bias ? bias[gn] : 0.f;
            if (gm0 < M) {
                float v = p.x * alpha + bb;
                if (DOGELU) v = 0.5f * v * (1.f + erff(v * 0.70710678118654752440f));
                if (res) v += res[(ll)gm0 * ldc + gn];
                C[(ll)gm0 * ldc + gn] = v;
            }
            if (gm1 < M) {
                float v = p.y * alpha + bb;
                if (DOGELU) v = 0.5f * v * (1.f + erff(v * 0.70710678118654752440f));
                if (res) v += res[(ll)gm1 * ldc + gn];
                C[(ll)gm1 * ldc + gn] = v;
            }
        }
    }
}

// ---------------- layernorm: one block per row, D=384 ------------------------
__global__ __launch_bounds__(128) void ln_k(
    const float* __restrict__ x, const float* __restrict__ g,
    const float* __restrict__ b, float* __restrict__ o)
{
    __shared__ float sh[4];
    ll row = blockIdx.x;
    const float* xr = x + row * DIM;
    float* orow = o + row * DIM;
    int t = threadIdx.x;

    float v0 = xr[t], v1 = xr[t + 128], v2 = xr[t + 256];
    float s = v0 + v1 + v2;
    #pragma unroll
    for (int ofs = 16; ofs; ofs >>= 1) s += __shfl_xor_sync(0xffffffffu, s, ofs);
    if ((t & 31) == 0) sh[t >> 5] = s;
    __syncthreads();
    float mean = (sh[0] + sh[1] + sh[2] + sh[3]) * (1.f / DIM);
    __syncthreads();

    float d0 = v0 - mean, d1 = v1 - mean, d2 = v2 - mean;
    float q = d0*d0 + d1*d1 + d2*d2;
    #pragma unroll
    for (int ofs = 16; ofs; ofs >>= 1) q += __shfl_xor_sync(0xffffffffu, q, ofs);
    if ((t & 31) == 0) sh[t >> 5] = q;
    __syncthreads();
    float var = (sh[0] + sh[1] + sh[2] + sh[3]) * (1.f / DIM);
    float r = rsqrtf(var + 1e-6f);

    orow[t]       = d0 * r * g[t]       + b[t];
    orow[t + 128] = d1 * r * g[t + 128] + b[t + 128];
    orow[t + 256] = d2 * r * g[t + 256] + b[t + 256];
}

// ---------------- softmax + threshold mask + renormalize (one block/row) -----
// Reference: p = softmax(s); keep p >= 0.1*max(p); p /= sum(kept).
// max(p) = exp(0)/sum = 1/sum exactly (exp(0)==1.0f), so thresh = 0.1f*(1/sum).
__global__ __launch_bounds__(256) void softmax_k(
    const float* __restrict__ S, float* __restrict__ P)
{
    __shared__ float sh[8];
    ll row = blockIdx.x;
    const float* sr = S + row * NTOK;
    float* pr = P + row * NTOK;
    int t = threadIdx.x;

    float v[4];
    float mx = -3.4e38f;
    #pragma unroll
    for (int i = 0; i < 4; i++) {
        int j = t + i * 256;
        v[i] = (j < NTOK) ? sr[j] : -3.4e38f;
        mx = fmaxf(mx, v[i]);
    }
    #pragma unroll
    for (int ofs = 16; ofs; ofs >>= 1) mx = fmaxf(mx, __shfl_xor_sync(0xffffffffu, mx, ofs));
    if ((t & 31) == 0) sh[t >> 5] = mx;
    __syncthreads();
    float smax = sh[0];
    #pragma unroll
    for (int i = 1; i < 8; i++) smax = fmaxf(smax, sh[i]);
    __syncthreads();

    float sum = 0.f;
    #pragma unroll
    for (int i = 0; i < 4; i++) {
        float e = expf(v[i] - smax);
        v[i] = e;
        sum += e;
    }
    #pragma unroll
    for (int ofs = 16; ofs; ofs >>= 1) sum += __shfl_xor_sync(0xffffffffu, sum, ofs);
    if ((t & 31) == 0) sh[t >> 5] = sum;
    __syncthreads();
    float S1 = sh[0] + sh[1] + sh[2] + sh[3] + sh[4] + sh[5] + sh[6] + sh[7];
    __syncthreads();

    float thresh = 0.1f * (1.0f / S1);
    float sum2 = 0.f;
    #pragma unroll
    for (int i = 0; i < 4; i++) {
        float p = v[i] / S1;
        v[i] = (p >= thresh) ? p : 0.f;
        sum2 += v[i];
    }
    #pragma unroll
    for (int ofs = 16; ofs; ofs >>= 1) sum2 += __shfl_xor_sync(0xffffffffu, sum2, ofs);
    if ((t & 31) == 0) sh[t >> 5] = sum2;
    __syncthreads();
    float S2 = sh[0] + sh[1] + sh[2] + sh[3] + sh[4] + sh[5] + sh[6] + sh[7];

    #pragma unroll
    for (int i = 0; i < 4; i++) {
        int j = t + i * 256;
        if (j < NTOK) pr[j] = v[i] / S2;
    }
}

__global__ void copy_k(const float* __restrict__ a, float* __restrict__ o, int n)
{
    int i = blockIdx.x * 256 + threadIdx.x;
    if (i < n) o[i] = a[i];
}

// -----------------------------------------------------------------------------
extern "C" void kernel_launch(void* const* d_in, const int* in_sizes, int n_in,
                              void* d_out, int out_size)
{
    const float* x_in   = (const float*)d_in[0];
    const float* w_qkv  = (const float*)d_in[1];
    const float* b_qkv  = (const float*)d_in[2];
    const float* w_proj = (const float*)d_in[3];
    const float* b_proj = (const float*)d_in[4];
    const float* ln1g   = (const float*)d_in[5];
    const float* ln1b   = (const float*)d_in[6];
    const float* ln2g   = (const float*)d_in[7];
    const float* ln2b   = (const float*)d_in[8];
    const float* w_fc1  = (const float*)d_in[9];
    const float* b_fc1  = (const float*)d_in[10];
    const float* w_fc2  = (const float*)d_in[11];
    const float* b_fc2  = (const float*)d_in[12];
    const float* lnfg   = (const float*)d_in[13];
    const float* lnfb   = (const float*)d_in[14];

    float* out_feat = (float*)d_out;
    float* out_attn = out_feat + FEAT_SIZE;

    float *x_, *ln_, *qkv_, *attn_, *ctx_, *hid_;
    cudaGetSymbolAddress((void**)&x_,   g_x);
    cudaGetSymbolAddress((void**)&ln_,  g_ln);
    cudaGetSymbolAddress((void**)&qkv_, g_qkv);
    cudaGetSymbolAddress((void**)&attn_, g_attn);
    cudaGetSymbolAddress((void**)&ctx_, g_ctx);
    cudaGetSymbolAddress((void**)&hid_, g_hid);

    copy_k<<<(FEAT_SIZE + 255) / 256, 256>>>(x_in, x_, FEAT_SIZE);

    const int mTc = (ROWS + 127) / 128;               // 16 M-tiles
    const int sBlk = (NTOK + TBM - 1) / TBM;          // 8

    for (int l = 0; l < NLAYER; l++) {
        // LN1
        ln_k<<<ROWS, 128>>>(x_, ln1g + l * DIM, ln1b + l * DIM, ln_);

        // QKV = ln1 @ w_qkv[l] + b_qkv[l]    [1924 x 1152], K=384  (HMMA)
        mma_gemm<false, false><<<dim3(QKVD / 64, mTc), 256>>>(
            ln_, w_qkv + (ll)l * DIM * QKVD, b_qkv + l * QKVD, nullptr, qkv_,
            ROWS, QKVD, DIM);

        // scores[b,h] = Q @ K^T * dh^-0.5   (12 batches of 962x962x64, FFMA2 exact)
        gemm_k<true, true, false><<<dim3((NTOK + TBN - 1) / TBN, sBlk, BATCH * NH), 256>>>(
            qkv_ /*Q*/, qkv_ + DIM /*K*/, nullptr, nullptr, attn_,
            NTOK, NTOK, DH, QKVD, QKVD, NTOK, NH,
            (ll)NTOK * QKVD, DH,
            (ll)NTOK * QKVD, DH,
            (ll)NH * NTOK * NTOK, (ll)NTOK * NTOK, 0.125f);

        // softmax + mask + renorm (last layer writes straight into d_out attn region)
        float* pdst = (l == NLAYER - 1) ? out_attn : attn_;
        softmax_k<<<BATCH * NH * NTOK, 256>>>(attn_, pdst);

        // ctx[b,n,h*64+d] = P @ V   (FFMA2, scalar-A path, K=962)
        gemm_k<false, false, false><<<dim3(1, sBlk, BATCH * NH), 256>>>(
            pdst, qkv_ + 2 * DIM /*V*/, nullptr, nullptr, ctx_,
            NTOK, DH, NTOK, NTOK, QKVD, DIM, NH,
            (ll)NH * NTOK * NTOK, (ll)NTOK * NTOK,
            (ll)NTOK * QKVD, DH,
            (ll)NTOK * DIM, DH, 1.f);

        // x += ctx @ w_proj[l] + b_proj[l]   [1924 x 384], K=384  (HMMA)
        mma_gemm<false, true><<<dim3(DIM / 64, mTc), 256>>>(
            ctx_, w_proj + (ll)l * DIM * DIM, b_proj + l * DIM, x_, x_,
            ROWS, DIM, DIM);

        // LN2
        ln_k<<<ROWS, 128>>>(x_, ln2g + l * DIM, ln2b + l * DIM, ln_);

        // hid = gelu(ln2 @ w_fc1[l] + b_fc1[l])   [1924 x 1536], K=384  (HMMA)
        mma_gemm<true, false><<<dim3(HIDD / 64, mTc), 256>>>(
            ln_, w_fc1 + (ll)l * DIM * HIDD, b_fc1 + l * HIDD, nullptr, hid_,
            ROWS, HIDD, DIM);

        // x += hid @ w_fc2[l] + b_fc2[l]   [1924 x 384], K=1536  (HMMA)
        mma_gemm<false, true><<<dim3(DIM / 64, mTc), 256>>>(
            hid_, w_fc2 + (ll)l * HIDD * DIM, b_fc2 + l * DIM, x_, x_,
            ROWS, DIM, HIDD);
    }

    // final LN -> feats
    ln_k<<<ROWS, 128>>>(x_, lnfg, lnfb, out_feat);
}

// round 13
// speedup vs baseline: 2.0912x; 1.2068x over previous
#include <cuda_runtime.h>
#include <cuda_bf16.h>
#include <math.h>

#define BATCH  2
#define NTOK   962
#define DIM    384
#define NH     6
#define DH     64
#define NLAYER 12
#define ROWS   (BATCH*NTOK)          // 1924
#define QKVD   (3*DIM)               // 1152
#define HIDD   (4*DIM)               // 1536
#define FEAT_SIZE (ROWS*DIM)         // 738816
#define SSTR   1024                  // padded row stride for scores/probs
#define NZ     (BATCH*NH)            // 12 attention batches

typedef unsigned long long u64;
typedef unsigned int u32;
typedef long long ll;

// ---------------- scratch (static device globals; no allocation) -------------
__device__ float g_x  [ROWS*DIM];
__device__ float g_ln [ROWS*DIM];
__device__ float g_qkv[ROWS*QKVD];
__device__ float g_attn [NZ*NTOK*SSTR];   // padded scores   (47 MB)
__device__ float g_attnp[NZ*NTOK*SSTR];   // padded probs    (47 MB)
__device__ float g_ctx[ROWS*DIM];
__device__ float g_hid[ROWS*HIDD];

// ---------------- bf16 split helpers -----------------------------------------
// split fp32 pair -> (hi bf16x2, lo bf16x2); element0 (x) in low 16 bits.
__device__ __forceinline__ void split2(float x, float y, u32& hi, u32& lo) {
    __nv_bfloat162 h = __floats2bfloat162_rn(x, y);
    float rx = x - __bfloat162float(h.x);
    float ry = y - __bfloat162float(h.y);
    __nv_bfloat162 l = __floats2bfloat162_rn(rx, ry);
    hi = *(u32*)&h; lo = *(u32*)&l;
}

// warp-level bf16 mma (base sm_80+ instruction; compiles for plain sm_103)
__device__ __forceinline__ void mma16816(float c[4],
    u32 a0, u32 a1, u32 a2, u32 a3, u32 b0, u32 b1)
{
    asm volatile(
        "mma.sync.aligned.m16n8k16.row.col.f32.bf16.bf16.f32 "
        "{%0,%1,%2,%3}, {%4,%5,%6,%7}, {%8,%9}, {%0,%1,%2,%3};"
        : "+f"(c[0]), "+f"(c[1]), "+f"(c[2]), "+f"(c[3])
        : "r"(a0), "r"(a1), "r"(a2), "r"(a3), "r"(b0), "r"(b1));
}

// shared-memory pair layout: per 8-pair group, column order [0,4,1,5,2,6,3,7]
// so fragment pairs (tg, tg+4) are one LDS.64; row stride 24 u32.
#define ASTR 24
__device__ __forceinline__ void pcol(int p0, int& c0, int& c1) {
    int s = p0 >> 3;
    int pg0 = p0 & 7, pg1 = (p0 + 1) & 7;
    c0 = s * 8 + ((pg0 & 3) * 2 + (pg0 >> 2));
    c1 = s * 8 + ((pg1 & 3) * 2 + (pg1 >> 2));
}

// ---------------- dense HMMA GEMM (bias/GELU/residual) -----------------------
// C[M,N] = act(A[M,K] @ B[K,N] + bias) + res.  A row-major lda=K, B row-major
// ldb=N, C row-major ldc=N.  K % 32 == 0, N % 64 == 0.
// CTA: 256 thr = 8 warps (4M x 2N); tile 128(M) x 64(N); K-chunks of 32.
// Split scheme: D += Ah*Bh + Ah*Bl + Al*Bh.
template<bool DOGELU, bool HASRES>
__global__ __launch_bounds__(256) void mma_gemm(
    const float* __restrict__ A, const float* __restrict__ B,
    const float* __restrict__ bias, const float* __restrict__ res,
    float* __restrict__ C, int M, int N, int K)
{
    __shared__ __align__(16) u32 Ah[128 * ASTR];
    __shared__ __align__(16) u32 Al[128 * ASTR];
    __shared__ __align__(16) u32 Bh[64 * ASTR];
    __shared__ __align__(16) u32 Bl[64 * ASTR];

    const int t = threadIdx.x;
    const int lane = t & 31, wid = t >> 5;
    const int g = lane >> 2, tg = lane & 3;
    const int mw = wid & 3, nw = wid >> 2;
    const int row0 = blockIdx.y * 128;
    const int n0 = blockIdx.x * 64;

    float acc[2][4][4];
    #pragma unroll
    for (int i = 0; i < 2; i++)
        #pragma unroll
        for (int j = 0; j < 4; j++)
            #pragma unroll
            for (int k = 0; k < 4; k++) acc[i][j][k] = 0.f;

    float4 Ar[4];
    float2 Br0[2], Br1[2];
    const int nC = K >> 5;

    auto LOADG = [&](int c) {
        int kb = c << 5;
        #pragma unroll
        for (int i = 0; i < 4; i++) {
            int id = t + (i << 8);
            int m = id >> 3, k4 = (id & 7) << 2;
            int gm = row0 + m;
            Ar[i] = (gm < M) ? *(const float4*)&A[(ll)gm * K + kb + k4]
                             : make_float4(0.f, 0.f, 0.f, 0.f);
        }
        #pragma unroll
        for (int i = 0; i < 2; i++) {
            int u = t + (i << 8);
            int kp = u >> 5, n2 = u & 31;
            const float* bp = &B[(ll)(kb + 2 * kp) * N + n0 + 2 * n2];
            Br0[i] = *(const float2*)bp;
            Br1[i] = *(const float2*)(bp + N);
        }
    };
    auto CONVST = [&]() {
        #pragma unroll
        for (int i = 0; i < 4; i++) {
            int id = t + (i << 8);
            int m = id >> 3, k4 = (id & 7) << 2;
            int c0, c1; pcol(k4 >> 1, c0, c1);
            u32 h0, l0, h1, l1;
            split2(Ar[i].x, Ar[i].y, h0, l0);
            split2(Ar[i].z, Ar[i].w, h1, l1);
            Ah[m * ASTR + c0] = h0; Ah[m * ASTR + c1] = h1;
            Al[m * ASTR + c0] = l0; Al[m * ASTR + c1] = l1;
        }
        #pragma unroll
        for (int i = 0; i < 2; i++) {
            int u = t + (i << 8);
            int kp = u >> 5, n2 = u & 31;
            int s = kp >> 3, pg = kp & 7;
            int cc = s * 8 + ((pg & 3) * 2 + (pg >> 2));
            u32 h0, l0, h1, l1;
            split2(Br0[i].x, Br1[i].x, h0, l0);
            split2(Br0[i].y, Br1[i].y, h1, l1);
            Bh[(2 * n2) * ASTR + cc] = h0;     Bl[(2 * n2) * ASTR + cc] = l0;
            Bh[(2 * n2 + 1) * ASTR + cc] = h1; Bl[(2 * n2 + 1) * ASTR + cc] = l1;
        }
    };

    LOADG(0); CONVST();
    __syncthreads();

    for (int c = 0; c < nC; c++) {
        const bool more = (c + 1 < nC);
        if (more) LOADG(c + 1);

        #pragma unroll
        for (int s = 0; s < 2; s++) {
            const int co = s * 8 + 2 * tg;
            uint2 AH0[2], AH1[2], AL0[2], AL1[2];
            #pragma unroll
            for (int mt = 0; mt < 2; mt++) {
                int rb = (mw * 32 + mt * 16 + g) * ASTR + co;
                AH0[mt] = *(const uint2*)&Ah[rb];
                AH1[mt] = *(const uint2*)&Ah[rb + 8 * ASTR];
                AL0[mt] = *(const uint2*)&Al[rb];
                AL1[mt] = *(const uint2*)&Al[rb + 8 * ASTR];
            }
            uint2 BHf[4], BLf[4];
            #pragma unroll
            for (int nt = 0; nt < 4; nt++) {
                int rb = (nw * 32 + nt * 8 + g) * ASTR + co;
                BHf[nt] = *(const uint2*)&Bh[rb];
                BLf[nt] = *(const uint2*)&Bl[rb];
            }
            #pragma unroll
            for (int mt = 0; mt < 2; mt++) {
                #pragma unroll
                for (int nt = 0; nt < 4; nt++) {
                    mma16816(acc[mt][nt], AH0[mt].x, AH1[mt].x, AH0[mt].y, AH1[mt].y,
                             BHf[nt].x, BHf[nt].y);
                    mma16816(acc[mt][nt], AH0[mt].x, AH1[mt].x, AH0[mt].y, AH1[mt].y,
                             BLf[nt].x, BLf[nt].y);
                    mma16816(acc[mt][nt], AL0[mt].x, AL1[mt].x, AL0[mt].y, AL1[mt].y,
                             BHf[nt].x, BHf[nt].y);
                }
            }
        }

        __syncthreads();
        if (more) {
            CONVST();
            __syncthreads();
        }
    }

    #pragma unroll
    for (int mt = 0; mt < 2; mt++) {
        #pragma unroll
        for (int half = 0; half < 2; half++) {
            int gm = row0 + mw * 32 + mt * 16 + half * 8 + g;
            if (gm >= M) continue;
            float* crow = &C[(ll)gm * N];
            const float* rrow = HASRES ? &res[(ll)gm * N] : nullptr;
            #pragma unroll
            for (int nt = 0; nt < 4; nt++) {
                int gn = n0 + nw * 32 + nt * 8 + 2 * tg;
                float v0 = acc[mt][nt][half * 2 + 0] + bias[gn];
                float v1 = acc[mt][nt][half * 2 + 1] + bias[gn + 1];
                if (DOGELU) {
                    v0 = 0.5f * v0 * (1.f + erff(v0 * 0.70710678118654752440f));
                    v1 = 0.5f * v1 * (1.f + erff(v1 * 0.70710678118654752440f));
                }
                if (HASRES) { v0 += rrow[gn]; v1 += rrow[gn + 1]; }
                *(float2*)&crow[gn] = make_float2(v0, v1);
            }
        }
    }
}

// ---------------- batched HMMA GEMM for attention (no bias/act) --------------
// TRANSB=true : C = alpha * A[M,K] @ B[N,K]^T   (QK^T; B rows guarded < Bvalid)
// TRANSB=false: C = alpha * A[M,K] @ B[K,N]     (PV; B k-rows guarded < Bvalid,
//                                                N fixed 64, gridDim.x == 1)
// K % 32 == 0. A row-major lda (A cols beyond data are caller-zeroed/padded).
// Batched over blockIdx.z = zb*Hn + zh.
template<bool TRANSB>
__global__ __launch_bounds__(256) void tmma(
    const float* __restrict__ A, const float* __restrict__ B,
    float* __restrict__ C,
    int M, int K, int lda, int ldb, int ldc, int Hn,
    ll sAb, ll sAh, ll sBb, ll sBh, ll sCb, ll sCh,
    float alpha, int Bvalid)
{
    __shared__ __align__(16) u32 Ah[128 * ASTR];
    __shared__ __align__(16) u32 Al[128 * ASTR];
    __shared__ __align__(16) u32 Bh[64 * ASTR];
    __shared__ __align__(16) u32 Bl[64 * ASTR];

    const int zb = blockIdx.z / Hn;
    const int zh = blockIdx.z % Hn;
    A += zb * sAb + zh * sAh;
    B += zb * sBb + zh * sBh;
    C += zb * sCb + zh * sCh;

    const int t = threadIdx.x;
    const int lane = t & 31, wid = t >> 5;
    const int g = lane >> 2, tg = lane & 3;
    const int mw = wid & 3, nw = wid >> 2;
    const int row0 = blockIdx.y * 128;
    const int n0 = blockIdx.x * 64;

    float acc[2][4][4];
    #pragma unroll
    for (int i = 0; i < 2; i++)
        #pragma unroll
        for (int j = 0; j < 4; j++)
            #pragma unroll
            for (int k = 0; k < 4; k++) acc[i][j][k] = 0.f;

    float4 Ar[4];
    float4 Brt[2];
    float2 Br0[2], Br1[2];
    const int nC = K >> 5;

    auto LOADG = [&](int c) {
        int kb = c << 5;
        #pragma unroll
        for (int i = 0; i < 4; i++) {
            int id = t + (i << 8);
            int m = id >> 3, k4 = (id & 7) << 2;
            int gm = row0 + m;
            Ar[i] = (gm < M) ? *(const float4*)&A[(ll)gm * lda + kb + k4]
                             : make_float4(0.f, 0.f, 0.f, 0.f);
        }
        if (TRANSB) {
            #pragma unroll
            for (int i = 0; i < 2; i++) {
                int id = t + (i << 8);
                int n = id >> 3, k4 = (id & 7) << 2;
                int gn = n0 + n;
                Brt[i] = (gn < Bvalid) ? *(const float4*)&B[(ll)gn * ldb + kb + k4]
                                       : make_float4(0.f, 0.f, 0.f, 0.f);
            }
        } else {
            #pragma unroll
            for (int i = 0; i < 2; i++) {
                int u = t + (i << 8);
                int kp = u >> 5, n2 = u & 31;
                int gk = kb + 2 * kp;
                Br0[i] = (gk < Bvalid) ? *(const float2*)&B[(ll)gk * ldb + 2 * n2]
                                       : make_float2(0.f, 0.f);
                Br1[i] = (gk + 1 < Bvalid)
                       ? *(const float2*)&B[(ll)(gk + 1) * ldb + 2 * n2]
                       : make_float2(0.f, 0.f);
            }
        }
    };
    auto CONVST = [&]() {
        #pragma unroll
        for (int i = 0; i < 4; i++) {
            int id = t + (i << 8);
            int m = id >> 3, k4 = (id & 7) << 2;
            int c0, c1; pcol(k4 >> 1, c0, c1);
            u32 h0, l0, h1, l1;
            split2(Ar[i].x, Ar[i].y, h0, l0);
            split2(Ar[i].z, Ar[i].w, h1, l1);
            Ah[m * ASTR + c0] = h0; Ah[m * ASTR + c1] = h1;
            Al[m * ASTR + c0] = l0; Al[m * ASTR + c1] = l1;
        }
        if (TRANSB) {
            #pragma unroll
            for (int i = 0; i < 2; i++) {
                int id = t + (i << 8);
                int n = id >> 3, k4 = (id & 7) << 2;
                int c0, c1; pcol(k4 >> 1, c0, c1);
                u32 h0, l0, h1, l1;
                split2(Brt[i].x, Brt[i].y, h0, l0);
                split2(Brt[i].z, Brt[i].w, h1, l1);
                Bh[n * ASTR + c0] = h0; Bh[n * ASTR + c1] = h1;
                Bl[n * ASTR + c0] = l0; Bl[n * ASTR + c1] = l1;
            }
        } else {
            #pragma unroll
            for (int i = 0; i < 2; i++) {
                int u = t + (i << 8);
                int kp = u >> 5, n2 = u & 31;
                int s = kp >> 3, pg = kp & 7;
                int cc = s * 8 + ((pg & 3) * 2 + (pg >> 2));
                u32 h0, l0, h1, l1;
                split2(Br0[i].x, Br1[i].x, h0, l0);
                split2(Br0[i].y, Br1[i].y, h1, l1);
                Bh[(2 * n2) * ASTR + cc] = h0;     Bl[(2 * n2) * ASTR + cc] = l0;
                Bh[(2 * n2 + 1) * ASTR + cc] = h1; Bl[(2 * n2 + 1) * ASTR + cc] = l1;
            }
        }
    };

    LOADG(0); CONVST();
    __syncthreads();

    for (int c = 0; c < nC; c++) {
        const bool more = (c + 1 < nC);
        if (more) LOADG(c + 1);

        #pragma unroll
        for (int s = 0; s < 2; s++) {
            const int co = s * 8 + 2 * tg;
            uint2 AH0[2], AH1[2], AL0[2], AL1[2];
            #pragma unroll
            for (int mt = 0; mt < 2; mt++) {
                int rb = (mw * 32 + mt * 16 + g) * ASTR + co;
                AH0[mt] = *(const uint2*)&Ah[rb];
                AH1[mt] = *(const uint2*)&Ah[rb + 8 * ASTR];
                AL0[mt] = *(const uint2*)&Al[rb];
                AL1[mt] = *(const uint2*)&Al[rb + 8 * ASTR];
            }
            uint2 BHf[4], BLf[4];
            #pragma unroll
            for (int nt = 0; nt < 4; nt++) {
                int rb = (nw * 32 + nt * 8 + g) * ASTR + co;
                BHf[nt] = *(const uint2*)&Bh[rb];
                BLf[nt] = *(const uint2*)&Bl[rb];
            }
            #pragma unroll
            for (int mt = 0; mt < 2; mt++) {
                #pragma unroll
                for (int nt = 0; nt < 4; nt++) {
                    mma16816(acc[mt][nt], AH0[mt].x, AH1[mt].x, AH0[mt].y, AH1[mt].y,
                             BHf[nt].x, BHf[nt].y);
                    mma16816(acc[mt][nt], AH0[mt].x, AH1[mt].x, AH0[mt].y, AH1[mt].y,
                             BLf[nt].x, BLf[nt].y);
                    mma16816(acc[mt][nt], AL0[mt].x, AL1[mt].x, AL0[mt].y, AL1[mt].y,
                             BHf[nt].x, BHf[nt].y);
                }
            }
        }

        __syncthreads();
        if (more) {
            CONVST();
            __syncthreads();
        }
    }

    #pragma unroll
    for (int mt = 0; mt < 2; mt++) {
        #pragma unroll
        for (int half = 0; half < 2; half++) {
            int gm = row0 + mw * 32 + mt * 16 + half * 8 + g;
            if (gm >= M) continue;
            float* crow = &C[(ll)gm * ldc];
            #pragma unroll
            for (int nt = 0; nt < 4; nt++) {
                int gn = n0 + nw * 32 + nt * 8 + 2 * tg;
                float v0 = acc[mt][nt][half * 2 + 0] * alpha;
                float v1 = acc[mt][nt][half * 2 + 1] * alpha;
                *(float2*)&crow[gn] = make_float2(v0, v1);
            }
        }
    }
}

// ---------------- layernorm: one block per row, D=384 ------------------------
__global__ __launch_bounds__(128) void ln_k(
    const float* __restrict__ x, const float* __restrict__ g,
    const float* __restrict__ b, float* __restrict__ o)
{
    __shared__ float sh[4];
    ll row = blockIdx.x;
    const float* xr = x + row * DIM;
    float* orow = o + row * DIM;
    int t = threadIdx.x;

    float v0 = xr[t], v1 = xr[t + 128], v2 = xr[t + 256];
    float s = v0 + v1 + v2;
    #pragma unroll
    for (int ofs = 16; ofs; ofs >>= 1) s += __shfl_xor_sync(0xffffffffu, s, ofs);
    if ((t & 31) == 0) sh[t >> 5] = s;
    __syncthreads();
    float mean = (sh[0] + sh[1] + sh[2] + sh[3]) * (1.f / DIM);
    __syncthreads();

    float d0 = v0 - mean, d1 = v1 - mean, d2 = v2 - mean;
    float q = d0*d0 + d1*d1 + d2*d2;
    #pragma unroll
    for (int ofs = 16; ofs; ofs >>= 1) q += __shfl_xor_sync(0xffffffffu, q, ofs);
    if ((t & 31) == 0) sh[t >> 5] = q;
    __syncthreads();
    float var = (sh[0] + sh[1] + sh[2] + sh[3]) * (1.f / DIM);
    float r = rsqrtf(var + 1e-6f);

    orow[t]       = d0 * r * g[t]       + b[t];
    orow[t + 128] = d1 * r * g[t + 128] + b[t + 128];
    orow[t + 256] = d2 * r * g[t + 256] + b[t + 256];
}

// ---------------- softmax + threshold mask + renormalize ---------------------
// p = softmax(s); keep p >= 0.1*max(p); renorm.  Since max(e) = exp(0) = 1,
// the compare p >= 0.1*max(p) is exactly e >= 0.1; output = e_kept / sum(e_kept).
// Reads padded scores (stride SSTR), writes padded probs (pad cols = 0) and
// optionally a compact 962-stride copy (last layer attn output).
__global__ __launch_bounds__(256) void softmax_k(
    const float* __restrict__ S, float* __restrict__ P, float* __restrict__ Pc)
{
    __shared__ float sh[8];
    ll row = blockIdx.x;
    const float* sr = S + row * SSTR;
    float* pr = P + row * SSTR;
    int t = threadIdx.x;

    float v[4];
    float mx = -3.4e38f;
    #pragma unroll
    for (int i = 0; i < 4; i++) {
        int j = t + i * 256;
        v[i] = (j < NTOK) ? sr[j] : -3.4e38f;
        mx = fmaxf(mx, v[i]);
    }
    #pragma unroll
    for (int ofs = 16; ofs; ofs >>= 1) mx = fmaxf(mx, __shfl_xor_sync(0xffffffffu, mx, ofs));
    if ((t & 31) == 0) sh[t >> 5] = mx;
    __syncthreads();
    float smax = sh[0];
    #pragma unroll
    for (int i = 1; i < 8; i++) smax = fmaxf(smax, sh[i]);
    __syncthreads();

    float sum = 0.f;
    #pragma unroll
    for (int i = 0; i < 4; i++) {
        int j = t + i * 256;
        float e = (j < NTOK) ? __expf(v[i] - smax) : 0.f;
        v[i] = (e >= 0.1f) ? e : 0.f;    // mask: e >= 0.1 == p >= 0.1*max(p)
        sum += v[i];
    }
    #pragma unroll
    for (int ofs = 16; ofs; ofs >>= 1) sum += __shfl_xor_sync(0xffffffffu, sum, ofs);
    if ((t & 31) == 0) sh[t >> 5] = sum;
    __syncthreads();
    float E2 = sh[0] + sh[1] + sh[2] + sh[3] + sh[4] + sh[5] + sh[6] + sh[7];
    float inv = 1.0f / E2;

    float* pcrow = Pc ? (Pc + row * NTOK) : nullptr;
    #pragma unroll
    for (int i = 0; i < 4; i++) {
        int j = t + i * 256;
        float o = v[i] * inv;
        pr[j] = o;                        // pad cols (>=962) get 0
        if (Pc && j < NTOK) pcrow[j] = o;
    }
}

__global__ void copy_k(const float* __restrict__ a, float* __restrict__ o, int n)
{
    int i = blockIdx.x * 256 + threadIdx.x;
    if (i < n) o[i] = a[i];
}

// -----------------------------------------------------------------------------
extern "C" void kernel_launch(void* const* d_in, const int* in_sizes, int n_in,
                              void* d_out, int out_size)
{
    const float* x_in   = (const float*)d_in[0];
    const float* w_qkv  = (const float*)d_in[1];
    const float* b_qkv  = (const float*)d_in[2];
    const float* w_proj = (const float*)d_in[3];
    const float* b_proj = (const float*)d_in[4];
    const float* ln1g   = (const float*)d_in[5];
    const float* ln1b   = (const float*)d_in[6];
    const float* ln2g   = (const float*)d_in[7];
    const float* ln2b   = (const float*)d_in[8];
    const float* w_fc1  = (const float*)d_in[9];
    const float* b_fc1  = (const float*)d_in[10];
    const float* w_fc2  = (const float*)d_in[11];
    const float* b_fc2  = (const float*)d_in[12];
    const float* lnfg   = (const float*)d_in[13];
    const float* lnfb   = (const float*)d_in[14];

    float* out_feat = (float*)d_out;
    float* out_attn = out_feat + FEAT_SIZE;

    float *x_, *ln_, *qkv_, *attn_, *attnp_, *ctx_, *hid_;
    cudaGetSymbolAddress((void**)&x_,    g_x);
    cudaGetSymbolAddress((void**)&ln_,   g_ln);
    cudaGetSymbolAddress((void**)&qkv_,  g_qkv);
    cudaGetSymbolAddress((void**)&attn_, g_attn);
    cudaGetSymbolAddress((void**)&attnp_, g_attnp);
    cudaGetSymbolAddress((void**)&ctx_,  g_ctx);
    cudaGetSymbolAddress((void**)&hid_,  g_hid);

    copy_k<<<(FEAT_SIZE + 255) / 256, 256>>>(x_in, x_, FEAT_SIZE);

    const int mTc = (ROWS + 127) / 128;       // 16 M-tiles (dense)
    const int yAt = (NTOK + 127) / 128;       // 8 M-tiles (attention)

    for (int l = 0; l < NLAYER; l++) {
        // LN1
        ln_k<<<ROWS, 128>>>(x_, ln1g + l * DIM, ln1b + l * DIM, ln_);

        // QKV = ln1 @ w_qkv[l] + b_qkv[l]    [1924 x 1152], K=384  (HMMA)
        mma_gemm<false, false><<<dim3(QKVD / 64, mTc), 256>>>(
            ln_, w_qkv + (ll)l * DIM * QKVD, b_qkv + l * QKVD, nullptr, qkv_,
            ROWS, QKVD, DIM);

        // scores[z] = 0.125 * Q @ K^T  (HMMA TRANSB; padded ldc=1024)
        tmma<true><<<dim3(SSTR / 64, yAt, NZ), 256>>>(
            qkv_ /*Q*/, qkv_ + DIM /*K*/, attn_,
            NTOK, DH, QKVD, QKVD, SSTR, NH,
            (ll)NTOK * QKVD, DH,
            (ll)NTOK * QKVD, DH,
            (ll)NH * NTOK * SSTR, (ll)NTOK * SSTR,
            0.125f, NTOK);

        // softmax + mask (e >= 0.1) + renorm -> padded probs (+compact last layer)
        float* pc = (l == NLAYER - 1) ? out_attn : nullptr;
        softmax_k<<<NZ * NTOK, 256>>>(attn_, attnp_, pc);

        // ctx = P @ V  (HMMA; A padded K=1024, V k-rows guarded)
        tmma<false><<<dim3(1, yAt, NZ), 256>>>(
            attnp_, qkv_ + 2 * DIM /*V*/, ctx_,
            NTOK, SSTR, SSTR, QKVD, DIM, NH,
            (ll)NH * NTOK * SSTR, (ll)NTOK * SSTR,
            (ll)NTOK * QKVD, DH,
            (ll)NTOK * DIM, DH,
            1.0f, NTOK);

        // x += ctx @ w_proj[l] + b_proj[l]   [1924 x 384], K=384  (HMMA)
        mma_gemm<false, true><<<dim3(DIM / 64, mTc), 256>>>(
            ctx_, w_proj + (ll)l * DIM * DIM, b_proj + l * DIM, x_, x_,
            ROWS, DIM, DIM);

        // LN2
        ln_k<<<ROWS, 128>>>(x_, ln2g + l * DIM, ln2b + l * DIM, ln_);

        // hid = gelu(ln2 @ w_fc1[l] + b_fc1[l])   [1924 x 1536], K=384  (HMMA)
        mma_gemm<true, false><<<dim3(HIDD / 64, mTc), 256>>>(
            ln_, w_fc1 + (ll)l * DIM * HIDD, b_fc1 + l * HIDD, nullptr, hid_,
            ROWS, HIDD, DIM);

        // x += hid @ w_fc2[l] + b_fc2[l]   [1924 x 384], K=1536  (HMMA)
        mma_gemm<false, true><<<dim3(DIM / 64, mTc), 256>>>(
            hid_, w_fc2 + (ll)l * HIDD * DIM, b_fc2 + l * DIM, x_, x_,
            ROWS, DIM, HIDD);
    }

    // final LN -> feats
    ln_k<<<ROWS, 128>>>(x_, lnfg, lnfb, out_feat);
}